// round 7
// baseline (speedup 1.0000x reference)
#include <cuda_runtime.h>
#include <math.h>

#define BB 2
#define SS 2048
#define DD 1024
#define HH 16
#define DP 64
#define MM (BB * SS)   // 4096
#define NZ (BB * HH)   // 32
#define KT (SS / 128)  // 16 k-tiles per row (scores tiling)

// Scratch (allocation-free rule: __device__ globals)
__device__ float g_q[MM * DD];
__device__ float g_k[MM * DD];
__device__ float g_v[MM * DD];
__device__ float g_c[MM * DD];
__device__ float g_pm[(size_t)NZ * SS * KT];   // per (row, ktile) partial max
__device__ float g_ps[(size_t)NZ * SS * KT];   // per (row, ktile) partial sumexp

// ---------------------------------------------------------------------------
// Helpers
// ---------------------------------------------------------------------------
__device__ __forceinline__ unsigned f2tf(float x) {
    unsigned r;
    asm("cvt.rna.tf32.f32 %0, %1;" : "=r"(r) : "f"(x));
    return r;
}

__device__ __forceinline__ void mma8(float* c, const unsigned* a, const unsigned* b) {
    asm volatile(
        "mma.sync.aligned.m16n8k8.row.col.f32.tf32.tf32.f32 "
        "{%0,%1,%2,%3}, {%4,%5,%6,%7}, {%8,%9}, {%0,%1,%2,%3};"
        : "+f"(c[0]), "+f"(c[1]), "+f"(c[2]), "+f"(c[3])
        : "r"(a[0]), "r"(a[1]), "r"(a[2]), "r"(a[3]), "r"(b[0]), "r"(b[1]));
}

__device__ __forceinline__ void ldm_x4(unsigned& r0, unsigned& r1,
                                       unsigned& r2, unsigned& r3, unsigned addr) {
    asm volatile("ldmatrix.sync.aligned.m8n8.x4.shared.b16 {%0,%1,%2,%3}, [%4];"
                 : "=r"(r0), "=r"(r1), "=r"(r2), "=r"(r3) : "r"(addr));
}

__device__ __forceinline__ unsigned smem_u32(const void* p) {
    unsigned r;
    asm("{ .reg .u64 t; cvta.to.shared.u64 t, %1; cvt.u32.u64 %0, t; }"
        : "=r"(r) : "l"(p));
    return r;
}

__device__ __forceinline__ void cpasync16(unsigned s, const void* g) {
    asm volatile("cp.async.cg.shared.global [%0], [%1], 16;" :: "r"(s), "l"(g));
}

// ---------------------------------------------------------------------------
// Pipelined tensor-core SGEMM + bias: tile 128x128, K-tile 32, 2-stage
// cp.async. A-fragments via ldmatrix (+cvt.rna), B scalar (+cvt.rna).
// ---------------------------------------------------------------------------
#define AS_STR 36
#define BS_STR 136
#define STG_F  (128 * AS_STR + 32 * BS_STR)   // 8960 floats/stage

__device__ __forceinline__ void gemm_load_tile(const float* __restrict__ A,
                                               const float* __restrict__ W,
                                               int Kdim, int Ndim,
                                               int m0, int n0, int k0,
                                               float* stage) {
    const int tid = threadIdx.x;
    unsigned sA = smem_u32(stage);
    unsigned sB = smem_u32(stage + 128 * AS_STR);
    #pragma unroll
    for (int i = tid; i < 1024; i += 256) {
        int r = i >> 3, c4 = (i & 7) * 4;
        cpasync16(sA + (r * AS_STR + c4) * 4, A + (size_t)(m0 + r) * Kdim + k0 + c4);
    }
    #pragma unroll
    for (int i = tid; i < 1024; i += 256) {
        int r = i >> 5, c4 = (i & 31) * 4;
        cpasync16(sB + (r * BS_STR + c4) * 4, W + (size_t)(k0 + r) * Ndim + n0 + c4);
    }
    asm volatile("cp.async.commit_group;");
}

__device__ __forceinline__ void gemm_body(const float* __restrict__ A,
                                          const float* __restrict__ W,
                                          const float* __restrict__ bias,
                                          float* __restrict__ C,
                                          int Ndim, int Kdim,
                                          int m0, int n0,
                                          float* smf) {
    const int tid = threadIdx.x;
    const int warp = tid >> 5, lane = tid & 31;
    const int g = lane >> 2, t = lane & 3;
    const int wm = warp >> 1, wn = warp & 1;
    const int lrow = lane & 15, lcol = (lane >> 4) * 4;   // ldmatrix addressing

    float acc[2][8][4] = {};

    gemm_load_tile(A, W, Kdim, Ndim, m0, n0, 0, smf);

    int s = 0;
    for (int k0 = 0; k0 < Kdim; k0 += 32, s ^= 1) {
        if (k0 + 32 < Kdim) {
            gemm_load_tile(A, W, Kdim, Ndim, m0, n0, k0 + 32, smf + (s ^ 1) * STG_F);
            asm volatile("cp.async.wait_group 1;");
        } else {
            asm volatile("cp.async.wait_group 0;");
        }
        __syncthreads();

        const float* As = smf + s * STG_F;
        const float* Bs = As + 128 * AS_STR;

        #pragma unroll
        for (int k = 0; k < 32; k += 8) {
            unsigned a[2][4], bfr[8][2];
            #pragma unroll
            for (int mt = 0; mt < 2; mt++) {
                int m = wm * 32 + mt * 16;
                unsigned raw[4];
                ldm_x4(raw[0], raw[1], raw[2], raw[3],
                       smem_u32(As + (m + lrow) * AS_STR + k + lcol));
                a[mt][0] = f2tf(__uint_as_float(raw[0]));
                a[mt][1] = f2tf(__uint_as_float(raw[1]));
                a[mt][2] = f2tf(__uint_as_float(raw[2]));
                a[mt][3] = f2tf(__uint_as_float(raw[3]));
            }
            #pragma unroll
            for (int nt = 0; nt < 8; nt++) {
                int n = wn * 64 + nt * 8 + g;
                bfr[nt][0] = f2tf(Bs[(k + t) * BS_STR + n]);
                bfr[nt][1] = f2tf(Bs[(k + t + 4) * BS_STR + n]);
            }
            #pragma unroll
            for (int mt = 0; mt < 2; mt++)
                #pragma unroll
                for (int nt = 0; nt < 8; nt++)
                    mma8(acc[mt][nt], a[mt], bfr[nt]);
        }
        __syncthreads();
    }

    #pragma unroll
    for (int mt = 0; mt < 2; mt++) {
        int row = m0 + wm * 32 + mt * 16 + g;
        #pragma unroll
        for (int nt = 0; nt < 8; nt++) {
            int col = n0 + wn * 64 + nt * 8 + 2 * t;
            float b0 = bias[col], b1 = bias[col + 1];
            C[(size_t)row * Ndim + col]           = acc[mt][nt][0] + b0;
            C[(size_t)row * Ndim + col + 1]       = acc[mt][nt][1] + b1;
            C[(size_t)(row + 8) * Ndim + col]     = acc[mt][nt][2] + b0;
            C[(size_t)(row + 8) * Ndim + col + 1] = acc[mt][nt][3] + b1;
        }
    }
}

#define GEMM_SMEM_BYTES (2 * STG_F * 4)   // 71680

__global__ void sgemm_bias_tc(const float* __restrict__ A,
                              const float* __restrict__ W,
                              const float* __restrict__ bias,
                              float* __restrict__ C,
                              int Ndim, int Kdim) {
    extern __shared__ float smf[];
    gemm_body(A, W, bias, C, Ndim, Kdim, blockIdx.y * 128, blockIdx.x * 128, smf);
}

__global__ void qkv_gemm_tc(const float* __restrict__ A0, const float* __restrict__ A1,
                            const float* __restrict__ A2,
                            const float* __restrict__ W0, const float* __restrict__ W1,
                            const float* __restrict__ W2,
                            const float* __restrict__ b0, const float* __restrict__ b1,
                            const float* __restrict__ b2,
                            float* __restrict__ C0, float* __restrict__ C1,
                            float* __restrict__ C2) {
    extern __shared__ float smf[];
    const int z = blockIdx.z;
    const float* A = (z == 0) ? A0 : (z == 1) ? A1 : A2;
    const float* W = (z == 0) ? W0 : (z == 1) ? W1 : W2;
    const float* bs = (z == 0) ? b0 : (z == 1) ? b1 : b2;
    float* C = (z == 0) ? C0 : (z == 1) ? C1 : C2;
    gemm_body(A, W, bs, C, DD, DD, blockIdx.y * 128, blockIdx.x * 128, smf);
}

// ---------------------------------------------------------------------------
// Attention scores + per-tile partial softmax stats. ldmatrix fragment loads
// for both A (Q) and B (K) — both tiles K-major [row][d], stride 68.
// ---------------------------------------------------------------------------
#define QS_STR 68
#define SCORES_SMEM_BYTES (2 * 128 * QS_STR * 4)
__global__ void attn_scores_tc(const float* __restrict__ Q,
                               const float* __restrict__ K,
                               const float* __restrict__ mask,
                               float* __restrict__ attn,
                               float* __restrict__ pm,
                               float* __restrict__ ps) {
    extern __shared__ unsigned sm[];
    unsigned* Qs = sm;                  // [128][68]
    unsigned* Ks = sm + 128 * QS_STR;   // [128][68]
    __shared__ float pmax[128 * 2];
    __shared__ float psum[128 * 2];

    const int z = blockIdx.z;
    const int b = z >> 4;
    const int h = z & 15;
    const int q0 = blockIdx.y * 128, k0 = blockIdx.x * 128;
    const int ktile = blockIdx.x;
    const int tid = threadIdx.x;
    const int warp = tid >> 5, lane = tid & 31;
    const int g = lane >> 2, t = lane & 3;
    const int wm = warp >> 1, wn = warp & 1;
    const int lrow = lane & 15, lcol = (lane >> 4) * 4;           // A ldmatrix
    const int brow = (lane & 7) + (lane >> 4) * 8;                // B ldmatrix
    const int bcol = ((lane >> 3) & 1) * 4;

    const float* Qb = Q + (size_t)(b * SS + q0) * DD + h * DP;
    const float* Kb = K + (size_t)(b * SS + k0) * DD + h * DP;

    #pragma unroll
    for (int i = tid; i < 128 * 16; i += 256) {
        int r = i >> 4, c4 = (i & 15) * 4;
        float4 vq = *(const float4*)(Qb + (size_t)r * DD + c4);
        float4 vk = *(const float4*)(Kb + (size_t)r * DD + c4);
        Qs[r * QS_STR + c4 + 0] = f2tf(vq.x);
        Qs[r * QS_STR + c4 + 1] = f2tf(vq.y);
        Qs[r * QS_STR + c4 + 2] = f2tf(vq.z);
        Qs[r * QS_STR + c4 + 3] = f2tf(vq.w);
        Ks[r * QS_STR + c4 + 0] = f2tf(vk.x);
        Ks[r * QS_STR + c4 + 1] = f2tf(vk.y);
        Ks[r * QS_STR + c4 + 2] = f2tf(vk.z);
        Ks[r * QS_STR + c4 + 3] = f2tf(vk.w);
    }
    __syncthreads();

    float acc[2][8][4] = {};
    #pragma unroll
    for (int k = 0; k < 64; k += 8) {
        unsigned a[2][4], bfr[8][2];
        #pragma unroll
        for (int mt = 0; mt < 2; mt++) {
            int m = wm * 32 + mt * 16;
            ldm_x4(a[mt][0], a[mt][1], a[mt][2], a[mt][3],
                   smem_u32(Qs + (m + lrow) * QS_STR + k + lcol));
        }
        #pragma unroll
        for (int pr = 0; pr < 4; pr++) {      // nt pairs (0,1),(2,3),(4,5),(6,7)
            int n0 = wn * 64 + pr * 16;
            ldm_x4(bfr[2 * pr][0], bfr[2 * pr][1], bfr[2 * pr + 1][0], bfr[2 * pr + 1][1],
                   smem_u32(Ks + (n0 + brow) * QS_STR + k + bcol));
        }
        #pragma unroll
        for (int mt = 0; mt < 2; mt++)
            #pragma unroll
            for (int nt = 0; nt < 8; nt++)
                mma8(acc[mt][nt], a[mt], bfr[nt]);
    }

    // scale + mask in registers
    #pragma unroll
    for (int mt = 0; mt < 2; mt++)
        #pragma unroll
        for (int nt = 0; nt < 8; nt++) {
            int kj = k0 + wn * 64 + nt * 8 + 2 * t;
            float mk0 = mask[b * SS + kj] * (-1e9f);
            float mk1 = mask[b * SS + kj + 1] * (-1e9f);
            acc[mt][nt][0] = acc[mt][nt][0] * 0.125f + mk0;
            acc[mt][nt][1] = acc[mt][nt][1] * 0.125f + mk1;
            acc[mt][nt][2] = acc[mt][nt][2] * 0.125f + mk0;
            acc[mt][nt][3] = acc[mt][nt][3] * 0.125f + mk1;
        }

    // write raw logits
    #pragma unroll
    for (int mt = 0; mt < 2; mt++) {
        int qi = q0 + wm * 32 + mt * 16 + g;
        size_t base0 = ((size_t)z * SS + qi) * SS;
        size_t base1 = base0 + (size_t)8 * SS;
        #pragma unroll
        for (int nt = 0; nt < 8; nt++) {
            int kj = k0 + wn * 64 + nt * 8 + 2 * t;
            attn[base0 + kj]     = acc[mt][nt][0];
            attn[base0 + kj + 1] = acc[mt][nt][1];
            attn[base1 + kj]     = acc[mt][nt][2];
            attn[base1 + kj + 1] = acc[mt][nt][3];
        }
    }

    // ---- per-tile partial stats ----
    #pragma unroll
    for (int mt = 0; mt < 2; mt++)
        #pragma unroll
        for (int hi = 0; hi < 2; hi++) {
            float mx = -1e30f;
            #pragma unroll
            for (int nt = 0; nt < 8; nt++)
                mx = fmaxf(mx, fmaxf(acc[mt][nt][2 * hi], acc[mt][nt][2 * hi + 1]));
            mx = fmaxf(mx, __shfl_xor_sync(~0u, mx, 1));
            mx = fmaxf(mx, __shfl_xor_sync(~0u, mx, 2));
            if (t == 0) pmax[(wm * 32 + mt * 16 + 8 * hi + g) * 2 + wn] = mx;
        }
    __syncthreads();

    #pragma unroll
    for (int mt = 0; mt < 2; mt++)
        #pragma unroll
        for (int hi = 0; hi < 2; hi++) {
            int row = wm * 32 + mt * 16 + 8 * hi + g;
            float tm = fmaxf(pmax[row * 2], pmax[row * 2 + 1]);
            float ls = 0.f;
            #pragma unroll
            for (int nt = 0; nt < 8; nt++)
                ls += __expf(acc[mt][nt][2 * hi] - tm) +
                      __expf(acc[mt][nt][2 * hi + 1] - tm);
            ls += __shfl_xor_sync(~0u, ls, 1);
            ls += __shfl_xor_sync(~0u, ls, 2);
            if (t == 0) psum[row * 2 + wn] = ls;
        }
    __syncthreads();

    if (tid < 128) {
        float m = fmaxf(pmax[tid * 2], pmax[tid * 2 + 1]);
        float ssum = psum[tid * 2] + psum[tid * 2 + 1];
        size_t idx = ((size_t)z * SS + q0 + tid) * KT + ktile;
        pm[idx] = m;
        ps[idx] = ssum;
    }
}

// ---------------------------------------------------------------------------
// Fused normalize + AV, v3: K-tile 64, 2-stage cp.async (104 KB -> 2 CTAs/SM),
// inline stats combine, ldmatrix P-fragment loads.
// Stage: raw P tile [128][68] (f32 -> tf32 in place) + V tile [64][68] (f32).
// ---------------------------------------------------------------------------
#define PS_STR 68
#define VS_STR 68
#define AV_STG_F (128 * PS_STR + 64 * VS_STR)   // 13056 floats/stage
#define AV_SMEM_BYTES (2 * AV_STG_F * 4)        // 104448

__device__ __forceinline__ void av_load_tile(const float* __restrict__ attn,
                                             const float* __restrict__ V,
                                             int z, int b, int h, int q0, int k0,
                                             float* stage) {
    const int tid = threadIdx.x;
    unsigned sP = smem_u32(stage);
    unsigned sV = smem_u32(stage + 128 * PS_STR);
    #pragma unroll
    for (int i = tid; i < 2048; i += 256) {       // 128 x 64 floats
        int r = i >> 4, c4 = (i & 15) * 4;
        cpasync16(sP + (r * PS_STR + c4) * 4,
                  attn + ((size_t)z * SS + q0 + r) * SS + k0 + c4);
    }
    #pragma unroll
    for (int i = tid; i < 1024; i += 256) {       // 64 x 64 floats
        int r = i >> 4, c4 = (i & 15) * 4;
        cpasync16(sV + (r * VS_STR + c4) * 4,
                  V + (size_t)(b * SS + k0 + r) * DD + h * DP + c4);
    }
    asm volatile("cp.async.commit_group;");
}

__global__ void __launch_bounds__(256, 2)
attn_av_norm(float* __restrict__ attn,
             const float* __restrict__ V,
             const float* __restrict__ pm,
             const float* __restrict__ ps,
             float* __restrict__ C) {
    extern __shared__ float smf[];
    __shared__ float rs[128], ri[128];

    const int z = blockIdx.y;
    const int b = z >> 4;
    const int h = z & 15;
    const int q0 = blockIdx.x * 128;
    const int tid = threadIdx.x;
    const int warp = tid >> 5, lane = tid & 31;
    const int g = lane >> 2, t = lane & 3;
    const int wm = warp >> 1, wn = warp & 1;
    const int lrow = lane & 15, lcol = (lane >> 4) * 4;

    av_load_tile(attn, V, z, b, h, q0, 0, smf);

    // inline combine of per-tile stats (one thread per row)
    if (tid < 128) {
        size_t base = ((size_t)z * SS + q0 + tid) * KT;
        float M = -1e30f;
        #pragma unroll
        for (int j = 0; j < KT; j++) M = fmaxf(M, pm[base + j]);
        float S = 0.f;
        #pragma unroll
        for (int j = 0; j < KT; j++) S += ps[base + j] * __expf(pm[base + j] - M);
        rs[tid] = M;
        ri[tid] = 1.0f / S;
    }
    __syncthreads();

    float acc[2][4][4] = {};
    int s = 0;
    for (int k0 = 0; k0 < SS; k0 += 64, s ^= 1) {
        if (k0 + 64 < SS) {
            av_load_tile(attn, V, z, b, h, q0, k0 + 64, smf + (s ^ 1) * AV_STG_F);
            asm volatile("cp.async.wait_group 1;");
        } else {
            asm volatile("cp.async.wait_group 0;");
        }
        __syncthreads();

        float* stage = smf + s * AV_STG_F;
        unsigned* stage_u = (unsigned*)stage;
        const float* Vs = stage + 128 * PS_STR;

        // exp + normalize: write global attn, overwrite smem with tf32 p
        #pragma unroll
        for (int i = tid; i < 2048; i += 256) {
            int r = i >> 4, c4 = (i & 15) * 4;
            float4 x = *(float4*)(stage + r * PS_STR + c4);
            float m = rs[r], inv = ri[r];
            x.x = __expf(x.x - m) * inv;
            x.y = __expf(x.y - m) * inv;
            x.z = __expf(x.z - m) * inv;
            x.w = __expf(x.w - m) * inv;
            *(float4*)(attn + ((size_t)z * SS + q0 + r) * SS + k0 + c4) = x;
            stage_u[r * PS_STR + c4 + 0] = f2tf(x.x);
            stage_u[r * PS_STR + c4 + 1] = f2tf(x.y);
            stage_u[r * PS_STR + c4 + 2] = f2tf(x.z);
            stage_u[r * PS_STR + c4 + 3] = f2tf(x.w);
        }
        __syncthreads();

        #pragma unroll
        for (int kk = 0; kk < 64; kk += 8) {
            unsigned a[2][4], bfr[4][2];
            #pragma unroll
            for (int mt = 0; mt < 2; mt++) {
                int m = wm * 32 + mt * 16;
                ldm_x4(a[mt][0], a[mt][1], a[mt][2], a[mt][3],
                       smem_u32(stage_u + (m + lrow) * PS_STR + kk + lcol));
            }
            #pragma unroll
            for (int nt = 0; nt < 4; nt++) {
                int n = wn * 32 + nt * 8 + g;
                bfr[nt][0] = f2tf(Vs[(kk + t) * VS_STR + n]);
                bfr[nt][1] = f2tf(Vs[(kk + t + 4) * VS_STR + n]);
            }
            #pragma unroll
            for (int mt = 0; mt < 2; mt++)
                #pragma unroll
                for (int nt = 0; nt < 4; nt++)
                    mma8(acc[mt][nt], a[mt], bfr[nt]);
        }
        __syncthreads();
    }

    #pragma unroll
    for (int mt = 0; mt < 2; mt++) {
        int qi = q0 + wm * 32 + mt * 16 + g;
        size_t base0 = (size_t)(b * SS + qi) * DD + h * DP;
        size_t base1 = base0 + (size_t)8 * DD;
        #pragma unroll
        for (int nt = 0; nt < 4; nt++) {
            int dj = wn * 32 + nt * 8 + 2 * t;
            C[base0 + dj]     = acc[mt][nt][0];
            C[base0 + dj + 1] = acc[mt][nt][1];
            C[base1 + dj]     = acc[mt][nt][2];
            C[base1 + dj + 1] = acc[mt][nt][3];
        }
    }
}

// ---------------------------------------------------------------------------
extern "C" void kernel_launch(void* const* d_in, const int* in_sizes, int n_in,
                              void* d_out, int out_size) {
    const float* q    = (const float*)d_in[0];
    const float* k    = (const float*)d_in[1];
    const float* v    = (const float*)d_in[2];
    const float* mask = (const float*)d_in[3];
    const float* Wq   = (const float*)d_in[4];
    const float* bq   = (const float*)d_in[5];
    const float* Wk   = (const float*)d_in[6];
    const float* bk   = (const float*)d_in[7];
    const float* Wv   = (const float*)d_in[8];
    const float* bv   = (const float*)d_in[9];
    const float* Wo   = (const float*)d_in[10];
    const float* bo   = (const float*)d_in[11];

    float* out  = (float*)d_out;
    float* attn = out + (size_t)MM * DD;   // output layout: (out, attn)

    float *pq, *pk, *pv, *pc, *ppm, *pps;
    cudaGetSymbolAddress((void**)&pq, g_q);
    cudaGetSymbolAddress((void**)&pk, g_k);
    cudaGetSymbolAddress((void**)&pv, g_v);
    cudaGetSymbolAddress((void**)&pc, g_c);
    cudaGetSymbolAddress((void**)&ppm, g_pm);
    cudaGetSymbolAddress((void**)&pps, g_ps);

    cudaFuncSetAttribute(qkv_gemm_tc, cudaFuncAttributeMaxDynamicSharedMemorySize,
                         GEMM_SMEM_BYTES);
    cudaFuncSetAttribute(sgemm_bias_tc, cudaFuncAttributeMaxDynamicSharedMemorySize,
                         GEMM_SMEM_BYTES);
    cudaFuncSetAttribute(attn_scores_tc, cudaFuncAttributeMaxDynamicSharedMemorySize,
                         SCORES_SMEM_BYTES);
    cudaFuncSetAttribute(attn_av_norm, cudaFuncAttributeMaxDynamicSharedMemorySize,
                         AV_SMEM_BYTES);

    dim3 gQKV(DD / 128, MM / 128, 3);               // (8, 32, 3)
    qkv_gemm_tc<<<gQKV, 256, GEMM_SMEM_BYTES>>>(q, k, v, Wq, Wk, Wv, bq, bk, bv,
                                                pq, pk, pv);

    dim3 gScores(SS / 128, SS / 128, NZ);           // (16, 16, 32)
    attn_scores_tc<<<gScores, 256, SCORES_SMEM_BYTES>>>(pq, pk, mask, attn, ppm, pps);

    dim3 gAV(SS / 128, NZ);                         // (16, 32)
    attn_av_norm<<<gAV, 256, AV_SMEM_BYTES>>>(attn, pv, ppm, pps, pc);

    dim3 gProj(DD / 128, MM / 128);                 // (8, 32)
    sgemm_bias_tc<<<gProj, 256, GEMM_SMEM_BYTES>>>(pc, Wo, bo, out, DD, DD);
}

// round 8
// speedup vs baseline: 1.5611x; 1.5611x over previous
#include <cuda_runtime.h>
#include <math.h>

#define BB 2
#define SS 2048
#define DD 1024
#define HH 16
#define DP 64
#define MM (BB * SS)   // 4096
#define NZ (BB * HH)   // 32
#define KT (SS / 128)  // 16 k-tiles per row (scores tiling)

// Scratch (allocation-free rule: __device__ globals)
__device__ float g_q[MM * DD];
__device__ float g_k[MM * DD];
__device__ float g_v[MM * DD];
__device__ float g_c[MM * DD];
__device__ float g_pm[(size_t)NZ * SS * KT];   // per (row, ktile) partial max
__device__ float g_ps[(size_t)NZ * SS * KT];   // per (row, ktile) partial sumexp

// ---------------------------------------------------------------------------
// Helpers
// ---------------------------------------------------------------------------
__device__ __forceinline__ unsigned f2tf(float x) {
    unsigned r;
    asm("cvt.rna.tf32.f32 %0, %1;" : "=r"(r) : "f"(x));
    return r;
}

__device__ __forceinline__ void mma8(float* c, const unsigned* a, const unsigned* b) {
    asm volatile(
        "mma.sync.aligned.m16n8k8.row.col.f32.tf32.tf32.f32 "
        "{%0,%1,%2,%3}, {%4,%5,%6,%7}, {%8,%9}, {%0,%1,%2,%3};"
        : "+f"(c[0]), "+f"(c[1]), "+f"(c[2]), "+f"(c[3])
        : "r"(a[0]), "r"(a[1]), "r"(a[2]), "r"(a[3]), "r"(b[0]), "r"(b[1]));
}

__device__ __forceinline__ unsigned smem_u32(const void* p) {
    unsigned r;
    asm("{ .reg .u64 t; cvta.to.shared.u64 t, %1; cvt.u32.u64 %0, t; }"
        : "=r"(r) : "l"(p));
    return r;
}

__device__ __forceinline__ void cpasync16(unsigned s, const void* g) {
    asm volatile("cp.async.cg.shared.global [%0], [%1], 16;" :: "r"(s), "l"(g));
}

// ---------------------------------------------------------------------------
// Pipelined tensor-core SGEMM + bias (round-5/6 proven): tile 128x128,
// K-tile 32, 2-stage cp.async double buffer, scalar fragment loads.
// ---------------------------------------------------------------------------
#define AS_STR 36
#define BS_STR 136
#define STG_F  (128 * AS_STR + 32 * BS_STR)   // 8960 floats/stage

__device__ __forceinline__ void gemm_load_tile(const float* __restrict__ A,
                                               const float* __restrict__ W,
                                               int Kdim, int Ndim,
                                               int m0, int n0, int k0,
                                               float* stage) {
    const int tid = threadIdx.x;
    unsigned sA = smem_u32(stage);
    unsigned sB = smem_u32(stage + 128 * AS_STR);
    #pragma unroll
    for (int i = tid; i < 1024; i += 256) {
        int r = i >> 3, c4 = (i & 7) * 4;
        cpasync16(sA + (r * AS_STR + c4) * 4, A + (size_t)(m0 + r) * Kdim + k0 + c4);
    }
    #pragma unroll
    for (int i = tid; i < 1024; i += 256) {
        int r = i >> 5, c4 = (i & 31) * 4;
        cpasync16(sB + (r * BS_STR + c4) * 4, W + (size_t)(k0 + r) * Ndim + n0 + c4);
    }
    asm volatile("cp.async.commit_group;");
}

__device__ __forceinline__ void gemm_body(const float* __restrict__ A,
                                          const float* __restrict__ W,
                                          const float* __restrict__ bias,
                                          float* __restrict__ C,
                                          int Ndim, int Kdim,
                                          int m0, int n0,
                                          float* smf) {
    const int tid = threadIdx.x;
    const int warp = tid >> 5, lane = tid & 31;
    const int g = lane >> 2, t = lane & 3;
    const int wm = warp >> 1, wn = warp & 1;

    float acc[2][8][4] = {};

    gemm_load_tile(A, W, Kdim, Ndim, m0, n0, 0, smf);

    int s = 0;
    for (int k0 = 0; k0 < Kdim; k0 += 32, s ^= 1) {
        if (k0 + 32 < Kdim) {
            gemm_load_tile(A, W, Kdim, Ndim, m0, n0, k0 + 32, smf + (s ^ 1) * STG_F);
            asm volatile("cp.async.wait_group 1;");
        } else {
            asm volatile("cp.async.wait_group 0;");
        }
        __syncthreads();

        const float* As = smf + s * STG_F;
        const float* Bs = As + 128 * AS_STR;

        #pragma unroll
        for (int k = 0; k < 32; k += 8) {
            unsigned a[2][4], bfr[8][2];
            #pragma unroll
            for (int mt = 0; mt < 2; mt++) {
                int m = wm * 32 + mt * 16;
                a[mt][0] = f2tf(As[(m + g) * AS_STR + k + t]);
                a[mt][1] = f2tf(As[(m + g + 8) * AS_STR + k + t]);
                a[mt][2] = f2tf(As[(m + g) * AS_STR + k + t + 4]);
                a[mt][3] = f2tf(As[(m + g + 8) * AS_STR + k + t + 4]);
            }
            #pragma unroll
            for (int nt = 0; nt < 8; nt++) {
                int n = wn * 64 + nt * 8 + g;
                bfr[nt][0] = f2tf(Bs[(k + t) * BS_STR + n]);
                bfr[nt][1] = f2tf(Bs[(k + t + 4) * BS_STR + n]);
            }
            #pragma unroll
            for (int mt = 0; mt < 2; mt++)
                #pragma unroll
                for (int nt = 0; nt < 8; nt++)
                    mma8(acc[mt][nt], a[mt], bfr[nt]);
        }
        __syncthreads();
    }

    #pragma unroll
    for (int mt = 0; mt < 2; mt++) {
        int row = m0 + wm * 32 + mt * 16 + g;
        #pragma unroll
        for (int nt = 0; nt < 8; nt++) {
            int col = n0 + wn * 64 + nt * 8 + 2 * t;
            float b0 = bias[col], b1 = bias[col + 1];
            C[(size_t)row * Ndim + col]           = acc[mt][nt][0] + b0;
            C[(size_t)row * Ndim + col + 1]       = acc[mt][nt][1] + b1;
            C[(size_t)(row + 8) * Ndim + col]     = acc[mt][nt][2] + b0;
            C[(size_t)(row + 8) * Ndim + col + 1] = acc[mt][nt][3] + b1;
        }
    }
}

#define GEMM_SMEM_BYTES (2 * STG_F * 4)   // 71680

__global__ void sgemm_bias_tc(const float* __restrict__ A,
                              const float* __restrict__ W,
                              const float* __restrict__ bias,
                              float* __restrict__ C,
                              int Ndim, int Kdim) {
    extern __shared__ float smf[];
    gemm_body(A, W, bias, C, Ndim, Kdim, blockIdx.y * 128, blockIdx.x * 128, smf);
}

__global__ void qkv_gemm_tc(const float* __restrict__ A0, const float* __restrict__ A1,
                            const float* __restrict__ A2,
                            const float* __restrict__ W0, const float* __restrict__ W1,
                            const float* __restrict__ W2,
                            const float* __restrict__ b0, const float* __restrict__ b1,
                            const float* __restrict__ b2,
                            float* __restrict__ C0, float* __restrict__ C1,
                            float* __restrict__ C2) {
    extern __shared__ float smf[];
    const int z = blockIdx.z;
    const float* A = (z == 0) ? A0 : (z == 1) ? A1 : A2;
    const float* W = (z == 0) ? W0 : (z == 1) ? W1 : W2;
    const float* bs = (z == 0) ? b0 : (z == 1) ? b1 : b2;
    float* C = (z == 0) ? C0 : (z == 1) ? C1 : C2;
    gemm_body(A, W, bs, C, DD, DD, blockIdx.y * 128, blockIdx.x * 128, smf);
}

// ---------------------------------------------------------------------------
// Attention scores + per-tile partial softmax stats (round-6 proven).
// Writes raw (scaled+masked) logits to attn, per (row, ktile) partials.
// ---------------------------------------------------------------------------
#define QS_STR 68
#define SCORES_SMEM_BYTES (2 * 128 * QS_STR * 4)
__global__ void attn_scores_tc(const float* __restrict__ Q,
                               const float* __restrict__ K,
                               const float* __restrict__ mask,
                               float* __restrict__ attn,
                               float* __restrict__ pm,
                               float* __restrict__ ps) {
    extern __shared__ unsigned sm[];
    unsigned* Qs = sm;                  // [128][68]
    unsigned* Ks = sm + 128 * QS_STR;   // [128][68]
    __shared__ float pmax[128 * 2];
    __shared__ float psum[128 * 2];

    const int z = blockIdx.z;
    const int b = z >> 4;
    const int h = z & 15;
    const int q0 = blockIdx.y * 128, k0 = blockIdx.x * 128;
    const int ktile = blockIdx.x;
    const int tid = threadIdx.x;
    const int warp = tid >> 5, lane = tid & 31;
    const int g = lane >> 2, t = lane & 3;
    const int wm = warp >> 1, wn = warp & 1;

    const float* Qb = Q + (size_t)(b * SS + q0) * DD + h * DP;
    const float* Kb = K + (size_t)(b * SS + k0) * DD + h * DP;

    #pragma unroll
    for (int i = tid; i < 128 * 16; i += 256) {
        int r = i >> 4, c4 = (i & 15) * 4;
        float4 vq = *(const float4*)(Qb + (size_t)r * DD + c4);
        float4 vk = *(const float4*)(Kb + (size_t)r * DD + c4);
        Qs[r * QS_STR + c4 + 0] = f2tf(vq.x);
        Qs[r * QS_STR + c4 + 1] = f2tf(vq.y);
        Qs[r * QS_STR + c4 + 2] = f2tf(vq.z);
        Qs[r * QS_STR + c4 + 3] = f2tf(vq.w);
        Ks[r * QS_STR + c4 + 0] = f2tf(vk.x);
        Ks[r * QS_STR + c4 + 1] = f2tf(vk.y);
        Ks[r * QS_STR + c4 + 2] = f2tf(vk.z);
        Ks[r * QS_STR + c4 + 3] = f2tf(vk.w);
    }
    __syncthreads();

    float acc[2][8][4] = {};
    #pragma unroll
    for (int k = 0; k < 64; k += 8) {
        unsigned a[2][4], bfr[8][2];
        #pragma unroll
        for (int mt = 0; mt < 2; mt++) {
            int m = wm * 32 + mt * 16;
            a[mt][0] = Qs[(m + g) * QS_STR + k + t];
            a[mt][1] = Qs[(m + g + 8) * QS_STR + k + t];
            a[mt][2] = Qs[(m + g) * QS_STR + k + t + 4];
            a[mt][3] = Qs[(m + g + 8) * QS_STR + k + t + 4];
        }
        #pragma unroll
        for (int nt = 0; nt < 8; nt++) {
            int n = wn * 64 + nt * 8 + g;
            bfr[nt][0] = Ks[n * QS_STR + k + t];
            bfr[nt][1] = Ks[n * QS_STR + k + t + 4];
        }
        #pragma unroll
        for (int mt = 0; mt < 2; mt++)
            #pragma unroll
            for (int nt = 0; nt < 8; nt++)
                mma8(acc[mt][nt], a[mt], bfr[nt]);
    }

    // scale + mask in registers
    #pragma unroll
    for (int mt = 0; mt < 2; mt++)
        #pragma unroll
        for (int nt = 0; nt < 8; nt++) {
            int kj = k0 + wn * 64 + nt * 8 + 2 * t;
            float mk0 = mask[b * SS + kj] * (-1e9f);
            float mk1 = mask[b * SS + kj + 1] * (-1e9f);
            acc[mt][nt][0] = acc[mt][nt][0] * 0.125f + mk0;
            acc[mt][nt][1] = acc[mt][nt][1] * 0.125f + mk1;
            acc[mt][nt][2] = acc[mt][nt][2] * 0.125f + mk0;
            acc[mt][nt][3] = acc[mt][nt][3] * 0.125f + mk1;
        }

    // write raw logits
    #pragma unroll
    for (int mt = 0; mt < 2; mt++) {
        int qi = q0 + wm * 32 + mt * 16 + g;
        size_t base0 = ((size_t)z * SS + qi) * SS;
        size_t base1 = base0 + (size_t)8 * SS;
        #pragma unroll
        for (int nt = 0; nt < 8; nt++) {
            int kj = k0 + wn * 64 + nt * 8 + 2 * t;
            attn[base0 + kj]     = acc[mt][nt][0];
            attn[base0 + kj + 1] = acc[mt][nt][1];
            attn[base1 + kj]     = acc[mt][nt][2];
            attn[base1 + kj + 1] = acc[mt][nt][3];
        }
    }

    // ---- per-tile partial stats ----
    #pragma unroll
    for (int mt = 0; mt < 2; mt++)
        #pragma unroll
        for (int hi = 0; hi < 2; hi++) {
            float mx = -1e30f;
            #pragma unroll
            for (int nt = 0; nt < 8; nt++)
                mx = fmaxf(mx, fmaxf(acc[mt][nt][2 * hi], acc[mt][nt][2 * hi + 1]));
            mx = fmaxf(mx, __shfl_xor_sync(~0u, mx, 1));
            mx = fmaxf(mx, __shfl_xor_sync(~0u, mx, 2));
            if (t == 0) pmax[(wm * 32 + mt * 16 + 8 * hi + g) * 2 + wn] = mx;
        }
    __syncthreads();

    #pragma unroll
    for (int mt = 0; mt < 2; mt++)
        #pragma unroll
        for (int hi = 0; hi < 2; hi++) {
            int row = wm * 32 + mt * 16 + 8 * hi + g;
            float tm = fmaxf(pmax[row * 2], pmax[row * 2 + 1]);
            float ls = 0.f;
            #pragma unroll
            for (int nt = 0; nt < 8; nt++)
                ls += __expf(acc[mt][nt][2 * hi] - tm) +
                      __expf(acc[mt][nt][2 * hi + 1] - tm);
            ls += __shfl_xor_sync(~0u, ls, 1);
            ls += __shfl_xor_sync(~0u, ls, 2);
            if (t == 0) psum[row * 2 + wn] = ls;
        }
    __syncthreads();

    if (tid < 128) {
        float m = fmaxf(pmax[tid * 2], pmax[tid * 2 + 1]);
        float ssum = psum[tid * 2] + psum[tid * 2 + 1];
        size_t idx = ((size_t)z * SS + q0 + tid) * KT + ktile;
        pm[idx] = m;
        ps[idx] = ssum;
    }
}

// ---------------------------------------------------------------------------
// Fused normalize + AV, v4: K-tile 64, 2-stage cp.async, 53 KB/stage ->
// 2 CTAs/SM. Inline stats combine. Scalar fragment loads (round-6 pattern).
// Stage: raw P tile [128][68] (f32 -> tf32 in place) + V tile [64][72] (f32).
// ---------------------------------------------------------------------------
#define PS_STR 68
#define VS_STR 72
#define AV_STG_F (128 * PS_STR + 64 * VS_STR)   // 13312 floats/stage
#define AV_SMEM_BYTES (2 * AV_STG_F * 4)        // 106496

__device__ __forceinline__ void av_load_tile(const float* __restrict__ attn,
                                             const float* __restrict__ V,
                                             int z, int b, int h, int q0, int k0,
                                             float* stage) {
    const int tid = threadIdx.x;
    unsigned sP = smem_u32(stage);
    unsigned sV = smem_u32(stage + 128 * PS_STR);
    #pragma unroll
    for (int i = tid; i < 2048; i += 256) {       // 128 x 64 floats
        int r = i >> 4, c4 = (i & 15) * 4;
        cpasync16(sP + (r * PS_STR + c4) * 4,
                  attn + ((size_t)z * SS + q0 + r) * SS + k0 + c4);
    }
    #pragma unroll
    for (int i = tid; i < 1024; i += 256) {       // 64 x 64 floats
        int r = i >> 4, c4 = (i & 15) * 4;
        cpasync16(sV + (r * VS_STR + c4) * 4,
                  V + (size_t)(b * SS + k0 + r) * DD + h * DP + c4);
    }
    asm volatile("cp.async.commit_group;");
}

__global__ void __launch_bounds__(256, 2)
attn_av_norm(float* __restrict__ attn,
             const float* __restrict__ V,
             const float* __restrict__ pm,
             const float* __restrict__ ps,
             float* __restrict__ C) {
    extern __shared__ float smf[];
    __shared__ float rs[128], ri[128];

    const int z = blockIdx.y;
    const int b = z >> 4;
    const int h = z & 15;
    const int q0 = blockIdx.x * 128;
    const int tid = threadIdx.x;
    const int warp = tid >> 5, lane = tid & 31;
    const int g = lane >> 2, t = lane & 3;
    const int wm = warp >> 1, wn = warp & 1;

    av_load_tile(attn, V, z, b, h, q0, 0, smf);

    // inline combine of per-tile stats (one thread per row)
    if (tid < 128) {
        size_t base = ((size_t)z * SS + q0 + tid) * KT;
        float M = -1e30f;
        #pragma unroll
        for (int j = 0; j < KT; j++) M = fmaxf(M, pm[base + j]);
        float S = 0.f;
        #pragma unroll
        for (int j = 0; j < KT; j++) S += ps[base + j] * __expf(pm[base + j] - M);
        rs[tid] = M;
        ri[tid] = 1.0f / S;
    }

    float acc[2][4][4] = {};
    int s = 0;
    for (int k0 = 0; k0 < SS; k0 += 64, s ^= 1) {
        if (k0 + 64 < SS) {
            av_load_tile(attn, V, z, b, h, q0, k0 + 64, smf + (s ^ 1) * AV_STG_F);
            asm volatile("cp.async.wait_group 1;");
        } else {
            asm volatile("cp.async.wait_group 0;");
        }
        __syncthreads();

        float* stage = smf + s * AV_STG_F;
        unsigned* stage_u = (unsigned*)stage;
        const float* Vs = stage + 128 * PS_STR;

        // exp + normalize: write global attn, overwrite smem with tf32 p
        #pragma unroll
        for (int i = tid; i < 2048; i += 256) {
            int r = i >> 4, c4 = (i & 15) * 4;
            float4 x = *(float4*)(stage + r * PS_STR + c4);
            float m = rs[r], inv = ri[r];
            x.x = __expf(x.x - m) * inv;
            x.y = __expf(x.y - m) * inv;
            x.z = __expf(x.z - m) * inv;
            x.w = __expf(x.w - m) * inv;
            *(float4*)(attn + ((size_t)z * SS + q0 + r) * SS + k0 + c4) = x;
            stage_u[r * PS_STR + c4 + 0] = f2tf(x.x);
            stage_u[r * PS_STR + c4 + 1] = f2tf(x.y);
            stage_u[r * PS_STR + c4 + 2] = f2tf(x.z);
            stage_u[r * PS_STR + c4 + 3] = f2tf(x.w);
        }
        __syncthreads();

        #pragma unroll
        for (int kk = 0; kk < 64; kk += 8) {
            unsigned a[2][4], bfr[4][2];
            #pragma unroll
            for (int mt = 0; mt < 2; mt++) {
                int m = wm * 32 + mt * 16;
                a[mt][0] = stage_u[(m + g) * PS_STR + kk + t];
                a[mt][1] = stage_u[(m + g + 8) * PS_STR + kk + t];
                a[mt][2] = stage_u[(m + g) * PS_STR + kk + t + 4];
                a[mt][3] = stage_u[(m + g + 8) * PS_STR + kk + t + 4];
            }
            #pragma unroll
            for (int nt = 0; nt < 4; nt++) {
                int n = wn * 32 + nt * 8 + g;
                bfr[nt][0] = f2tf(Vs[(kk + t) * VS_STR + n]);
                bfr[nt][1] = f2tf(Vs[(kk + t + 4) * VS_STR + n]);
            }
            #pragma unroll
            for (int mt = 0; mt < 2; mt++)
                #pragma unroll
                for (int nt = 0; nt < 4; nt++)
                    mma8(acc[mt][nt], a[mt], bfr[nt]);
        }
        __syncthreads();
    }

    #pragma unroll
    for (int mt = 0; mt < 2; mt++) {
        int qi = q0 + wm * 32 + mt * 16 + g;
        size_t base0 = (size_t)(b * SS + qi) * DD + h * DP;
        size_t base1 = base0 + (size_t)8 * DD;
        #pragma unroll
        for (int nt = 0; nt < 4; nt++) {
            int dj = wn * 32 + nt * 8 + 2 * t;
            C[base0 + dj]     = acc[mt][nt][0];
            C[base0 + dj + 1] = acc[mt][nt][1];
            C[base1 + dj]     = acc[mt][nt][2];
            C[base1 + dj + 1] = acc[mt][nt][3];
        }
    }
}

// ---------------------------------------------------------------------------
extern "C" void kernel_launch(void* const* d_in, const int* in_sizes, int n_in,
                              void* d_out, int out_size) {
    const float* q    = (const float*)d_in[0];
    const float* k    = (const float*)d_in[1];
    const float* v    = (const float*)d_in[2];
    const float* mask = (const float*)d_in[3];
    const float* Wq   = (const float*)d_in[4];
    const float* bq   = (const float*)d_in[5];
    const float* Wk   = (const float*)d_in[6];
    const float* bk   = (const float*)d_in[7];
    const float* Wv   = (const float*)d_in[8];
    const float* bv   = (const float*)d_in[9];
    const float* Wo   = (const float*)d_in[10];
    const float* bo   = (const float*)d_in[11];

    float* out  = (float*)d_out;
    float* attn = out + (size_t)MM * DD;   // output layout: (out, attn)

    float *pq, *pk, *pv, *pc, *ppm, *pps;
    cudaGetSymbolAddress((void**)&pq, g_q);
    cudaGetSymbolAddress((void**)&pk, g_k);
    cudaGetSymbolAddress((void**)&pv, g_v);
    cudaGetSymbolAddress((void**)&pc, g_c);
    cudaGetSymbolAddress((void**)&ppm, g_pm);
    cudaGetSymbolAddress((void**)&pps, g_ps);

    cudaFuncSetAttribute(qkv_gemm_tc, cudaFuncAttributeMaxDynamicSharedMemorySize,
                         GEMM_SMEM_BYTES);
    cudaFuncSetAttribute(sgemm_bias_tc, cudaFuncAttributeMaxDynamicSharedMemorySize,
                         GEMM_SMEM_BYTES);
    cudaFuncSetAttribute(attn_scores_tc, cudaFuncAttributeMaxDynamicSharedMemorySize,
                         SCORES_SMEM_BYTES);
    cudaFuncSetAttribute(attn_av_norm, cudaFuncAttributeMaxDynamicSharedMemorySize,
                         AV_SMEM_BYTES);

    dim3 gQKV(DD / 128, MM / 128, 3);               // (8, 32, 3)
    qkv_gemm_tc<<<gQKV, 256, GEMM_SMEM_BYTES>>>(q, k, v, Wq, Wk, Wv, bq, bk, bv,
                                                pq, pk, pv);

    dim3 gScores(SS / 128, SS / 128, NZ);           // (16, 16, 32)
    attn_scores_tc<<<gScores, 256, SCORES_SMEM_BYTES>>>(pq, pk, mask, attn, ppm, pps);

    dim3 gAV(SS / 128, NZ);                         // (16, 32)
    attn_av_norm<<<gAV, 256, AV_SMEM_BYTES>>>(attn, pv, ppm, pps, pc);

    dim3 gProj(DD / 128, MM / 128);                 // (8, 32)
    sgemm_bias_tc<<<gProj, 256, GEMM_SMEM_BYTES>>>(pc, Wo, bo, out, DD, DD);
}

// round 9
// speedup vs baseline: 1.5744x; 1.0085x over previous
#include <cuda_runtime.h>
#include <math.h>

#define BB 2
#define SS 2048
#define DD 1024
#define HH 16
#define DP 64
#define MM (BB * SS)   // 4096
#define NZ (BB * HH)   // 32
#define KT (SS / 128)  // 16 k-tiles per row (scores tiling)

// Scratch (allocation-free rule: __device__ globals)
__device__ float g_q[MM * DD];                 // qh (tf32-rounded)
__device__ float g_k[MM * DD];                 // kh (tf32-rounded)
__device__ float g_v[MM * DD];                 // vh (tf32-rounded)
__device__ float g_c[MM * DD];                 // ctx (tf32-rounded)
__device__ float g_iq[MM * DD];                // q input, tf32-rounded
__device__ float g_ik[MM * DD];
__device__ float g_iv[MM * DD];
__device__ float g_wt[4 * DD * DD];            // Wq,Wk,Wv,Wo tf32-rounded
__device__ float g_pm[(size_t)NZ * SS * KT];   // per (row, ktile) partial max
__device__ float g_ps[(size_t)NZ * SS * KT];   // per (row, ktile) partial sumexp

// ---------------------------------------------------------------------------
// Helpers
// ---------------------------------------------------------------------------
__device__ __forceinline__ unsigned f2tf(float x) {
    unsigned r;
    asm("cvt.rna.tf32.f32 %0, %1;" : "=r"(r) : "f"(x));
    return r;
}
__device__ __forceinline__ float f2tff(float x) { return __uint_as_float(f2tf(x)); }

__device__ __forceinline__ void mma8(float* c, const unsigned* a, const unsigned* b) {
    asm volatile(
        "mma.sync.aligned.m16n8k8.row.col.f32.tf32.tf32.f32 "
        "{%0,%1,%2,%3}, {%4,%5,%6,%7}, {%8,%9}, {%0,%1,%2,%3};"
        : "+f"(c[0]), "+f"(c[1]), "+f"(c[2]), "+f"(c[3])
        : "r"(a[0]), "r"(a[1]), "r"(a[2]), "r"(a[3]), "r"(b[0]), "r"(b[1]));
}

__device__ __forceinline__ unsigned smem_u32(const void* p) {
    unsigned r;
    asm("{ .reg .u64 t; cvta.to.shared.u64 t, %1; cvt.u32.u64 %0, t; }"
        : "=r"(r) : "l"(p));
    return r;
}

__device__ __forceinline__ void cpasync16(unsigned s, const void* g) {
    asm volatile("cp.async.cg.shared.global [%0], [%1], 16;" :: "r"(s), "l"(g));
}

// ---------------------------------------------------------------------------
// One-shot tf32 pre-rounding of all GEMM inputs (inputs q,k,v + 4 weights).
// ---------------------------------------------------------------------------
__global__ void cvt_all(const float* __restrict__ q, const float* __restrict__ k,
                        const float* __restrict__ v,
                        const float* __restrict__ Wq, const float* __restrict__ Wk,
                        const float* __restrict__ Wv, const float* __restrict__ Wo,
                        float* __restrict__ iq, float* __restrict__ ik,
                        float* __restrict__ iv, float* __restrict__ wt) {
    const int seg = blockIdx.y;
    const float* src;
    float* dst;
    int n;
    if (seg == 0)      { src = q;  dst = iq; n = MM * DD; }
    else if (seg == 1) { src = k;  dst = ik; n = MM * DD; }
    else if (seg == 2) { src = v;  dst = iv; n = MM * DD; }
    else {
        int w = seg - 3;
        src = (w == 0) ? Wq : (w == 1) ? Wk : (w == 2) ? Wv : Wo;
        dst = wt + (size_t)w * DD * DD;
        n = DD * DD;
    }
    int i = (blockIdx.x * 256 + threadIdx.x) * 4;
    if (i < n) {
        float4 x = *(const float4*)(src + i);
        x.x = f2tff(x.x); x.y = f2tff(x.y); x.z = f2tff(x.z); x.w = f2tff(x.w);
        *(float4*)(dst + i) = x;
    }
}

// ---------------------------------------------------------------------------
// Pipelined tensor-core GEMM + bias on pre-rounded tf32 data: tile 128x128,
// K-tile 32, 2-stage cp.async. NO cvt in the inner loop. CVT_OUT rounds the
// epilogue output to tf32 when the consumer is another MMA.
// ---------------------------------------------------------------------------
#define AS_STR 36
#define BS_STR 136
#define STG_F  (128 * AS_STR + 32 * BS_STR)   // 8960 floats/stage

__device__ __forceinline__ void gemm_load_tile(const float* __restrict__ A,
                                               const float* __restrict__ W,
                                               int Kdim, int Ndim,
                                               int m0, int n0, int k0,
                                               float* stage) {
    const int tid = threadIdx.x;
    unsigned sA = smem_u32(stage);
    unsigned sB = smem_u32(stage + 128 * AS_STR);
    #pragma unroll
    for (int i = tid; i < 1024; i += 256) {
        int r = i >> 3, c4 = (i & 7) * 4;
        cpasync16(sA + (r * AS_STR + c4) * 4, A + (size_t)(m0 + r) * Kdim + k0 + c4);
    }
    #pragma unroll
    for (int i = tid; i < 1024; i += 256) {
        int r = i >> 5, c4 = (i & 31) * 4;
        cpasync16(sB + (r * BS_STR + c4) * 4, W + (size_t)(k0 + r) * Ndim + n0 + c4);
    }
    asm volatile("cp.async.commit_group;");
}

template <bool CVT_OUT>
__device__ __forceinline__ void gemm_body(const float* __restrict__ A,
                                          const float* __restrict__ W,
                                          const float* __restrict__ bias,
                                          float* __restrict__ C,
                                          int Ndim, int Kdim,
                                          int m0, int n0,
                                          float* smf) {
    const int tid = threadIdx.x;
    const int warp = tid >> 5, lane = tid & 31;
    const int g = lane >> 2, t = lane & 3;
    const int wm = warp >> 1, wn = warp & 1;

    float acc[2][8][4] = {};

    gemm_load_tile(A, W, Kdim, Ndim, m0, n0, 0, smf);

    int s = 0;
    for (int k0 = 0; k0 < Kdim; k0 += 32, s ^= 1) {
        if (k0 + 32 < Kdim) {
            gemm_load_tile(A, W, Kdim, Ndim, m0, n0, k0 + 32, smf + (s ^ 1) * STG_F);
            asm volatile("cp.async.wait_group 1;");
        } else {
            asm volatile("cp.async.wait_group 0;");
        }
        __syncthreads();

        const unsigned* As = (const unsigned*)(smf + s * STG_F);
        const unsigned* Bs = As + 128 * AS_STR;

        #pragma unroll
        for (int k = 0; k < 32; k += 8) {
            unsigned a[2][4], bfr[8][2];
            #pragma unroll
            for (int mt = 0; mt < 2; mt++) {
                int m = wm * 32 + mt * 16;
                a[mt][0] = As[(m + g) * AS_STR + k + t];
                a[mt][1] = As[(m + g + 8) * AS_STR + k + t];
                a[mt][2] = As[(m + g) * AS_STR + k + t + 4];
                a[mt][3] = As[(m + g + 8) * AS_STR + k + t + 4];
            }
            #pragma unroll
            for (int nt = 0; nt < 8; nt++) {
                int n = wn * 64 + nt * 8 + g;
                bfr[nt][0] = Bs[(k + t) * BS_STR + n];
                bfr[nt][1] = Bs[(k + t + 4) * BS_STR + n];
            }
            #pragma unroll
            for (int mt = 0; mt < 2; mt++)
                #pragma unroll
                for (int nt = 0; nt < 8; nt++)
                    mma8(acc[mt][nt], a[mt], bfr[nt]);
        }
        __syncthreads();
    }

    #pragma unroll
    for (int mt = 0; mt < 2; mt++) {
        int row = m0 + wm * 32 + mt * 16 + g;
        #pragma unroll
        for (int nt = 0; nt < 8; nt++) {
            int col = n0 + wn * 64 + nt * 8 + 2 * t;
            float b0 = bias[col], b1 = bias[col + 1];
            float o00 = acc[mt][nt][0] + b0, o01 = acc[mt][nt][1] + b1;
            float o10 = acc[mt][nt][2] + b0, o11 = acc[mt][nt][3] + b1;
            if (CVT_OUT) {
                o00 = f2tff(o00); o01 = f2tff(o01);
                o10 = f2tff(o10); o11 = f2tff(o11);
            }
            C[(size_t)row * Ndim + col]           = o00;
            C[(size_t)row * Ndim + col + 1]       = o01;
            C[(size_t)(row + 8) * Ndim + col]     = o10;
            C[(size_t)(row + 8) * Ndim + col + 1] = o11;
        }
    }
}

#define GEMM_SMEM_BYTES (2 * STG_F * 4)   // 71680

__global__ void __launch_bounds__(256, 2)
sgemm_bias_tc(const float* __restrict__ A, const float* __restrict__ W,
              const float* __restrict__ bias, float* __restrict__ C,
              int Ndim, int Kdim) {
    extern __shared__ float smf[];
    gemm_body<false>(A, W, bias, C, Ndim, Kdim,
                     blockIdx.y * 128, blockIdx.x * 128, smf);
}

__global__ void __launch_bounds__(256, 2)
qkv_gemm_tc(const float* __restrict__ A0, const float* __restrict__ A1,
            const float* __restrict__ A2, const float* __restrict__ Wt,
            const float* __restrict__ b0, const float* __restrict__ b1,
            const float* __restrict__ b2,
            float* __restrict__ C0, float* __restrict__ C1,
            float* __restrict__ C2) {
    extern __shared__ float smf[];
    const int z = blockIdx.z;
    const float* A = (z == 0) ? A0 : (z == 1) ? A1 : A2;
    const float* W = Wt + (size_t)z * DD * DD;
    const float* bs = (z == 0) ? b0 : (z == 1) ? b1 : b2;
    float* C = (z == 0) ? C0 : (z == 1) ? C1 : C2;
    gemm_body<true>(A, W, bs, C, DD, DD, blockIdx.y * 128, blockIdx.x * 128, smf);
}

// ---------------------------------------------------------------------------
// Attention scores + per-tile partial softmax stats. Q/K are pre-rounded
// tf32 -> straight bit copies into smem, no cvt anywhere.
// ---------------------------------------------------------------------------
#define QS_STR 68
#define SCORES_SMEM_BYTES (2 * 128 * QS_STR * 4)
__global__ void attn_scores_tc(const float* __restrict__ Q,
                               const float* __restrict__ K,
                               const float* __restrict__ mask,
                               float* __restrict__ attn,
                               float* __restrict__ pm,
                               float* __restrict__ ps) {
    extern __shared__ unsigned sm[];
    unsigned* Qs = sm;                  // [128][68]
    unsigned* Ks = sm + 128 * QS_STR;   // [128][68]
    __shared__ float pmax[128 * 2];
    __shared__ float psum[128 * 2];

    const int z = blockIdx.z;
    const int b = z >> 4;
    const int h = z & 15;
    const int q0 = blockIdx.y * 128, k0 = blockIdx.x * 128;
    const int ktile = blockIdx.x;
    const int tid = threadIdx.x;
    const int warp = tid >> 5, lane = tid & 31;
    const int g = lane >> 2, t = lane & 3;
    const int wm = warp >> 1, wn = warp & 1;

    const uint4* Qb = (const uint4*)(Q + (size_t)(b * SS + q0) * DD + h * DP);
    const uint4* Kb = (const uint4*)(K + (size_t)(b * SS + k0) * DD + h * DP);

    #pragma unroll
    for (int i = tid; i < 128 * 16; i += 256) {
        int r = i >> 4, c4i = i & 15;
        uint4 vq = Qb[r * (DD / 4) + c4i];
        uint4 vk = Kb[r * (DD / 4) + c4i];
        int c4 = c4i * 4;
        Qs[r * QS_STR + c4 + 0] = vq.x;
        Qs[r * QS_STR + c4 + 1] = vq.y;
        Qs[r * QS_STR + c4 + 2] = vq.z;
        Qs[r * QS_STR + c4 + 3] = vq.w;
        Ks[r * QS_STR + c4 + 0] = vk.x;
        Ks[r * QS_STR + c4 + 1] = vk.y;
        Ks[r * QS_STR + c4 + 2] = vk.z;
        Ks[r * QS_STR + c4 + 3] = vk.w;
    }
    __syncthreads();

    float acc[2][8][4] = {};
    #pragma unroll
    for (int k = 0; k < 64; k += 8) {
        unsigned a[2][4], bfr[8][2];
        #pragma unroll
        for (int mt = 0; mt < 2; mt++) {
            int m = wm * 32 + mt * 16;
            a[mt][0] = Qs[(m + g) * QS_STR + k + t];
            a[mt][1] = Qs[(m + g + 8) * QS_STR + k + t];
            a[mt][2] = Qs[(m + g) * QS_STR + k + t + 4];
            a[mt][3] = Qs[(m + g + 8) * QS_STR + k + t + 4];
        }
        #pragma unroll
        for (int nt = 0; nt < 8; nt++) {
            int n = wn * 64 + nt * 8 + g;
            bfr[nt][0] = Ks[n * QS_STR + k + t];
            bfr[nt][1] = Ks[n * QS_STR + k + t + 4];
        }
        #pragma unroll
        for (int mt = 0; mt < 2; mt++)
            #pragma unroll
            for (int nt = 0; nt < 8; nt++)
                mma8(acc[mt][nt], a[mt], bfr[nt]);
    }

    // scale + mask in registers
    #pragma unroll
    for (int mt = 0; mt < 2; mt++)
        #pragma unroll
        for (int nt = 0; nt < 8; nt++) {
            int kj = k0 + wn * 64 + nt * 8 + 2 * t;
            float mk0 = mask[b * SS + kj] * (-1e9f);
            float mk1 = mask[b * SS + kj + 1] * (-1e9f);
            acc[mt][nt][0] = acc[mt][nt][0] * 0.125f + mk0;
            acc[mt][nt][1] = acc[mt][nt][1] * 0.125f + mk1;
            acc[mt][nt][2] = acc[mt][nt][2] * 0.125f + mk0;
            acc[mt][nt][3] = acc[mt][nt][3] * 0.125f + mk1;
        }

    // write raw logits
    #pragma unroll
    for (int mt = 0; mt < 2; mt++) {
        int qi = q0 + wm * 32 + mt * 16 + g;
        size_t base0 = ((size_t)z * SS + qi) * SS;
        size_t base1 = base0 + (size_t)8 * SS;
        #pragma unroll
        for (int nt = 0; nt < 8; nt++) {
            int kj = k0 + wn * 64 + nt * 8 + 2 * t;
            attn[base0 + kj]     = acc[mt][nt][0];
            attn[base0 + kj + 1] = acc[mt][nt][1];
            attn[base1 + kj]     = acc[mt][nt][2];
            attn[base1 + kj + 1] = acc[mt][nt][3];
        }
    }

    // ---- per-tile partial stats ----
    #pragma unroll
    for (int mt = 0; mt < 2; mt++)
        #pragma unroll
        for (int hi = 0; hi < 2; hi++) {
            float mx = -1e30f;
            #pragma unroll
            for (int nt = 0; nt < 8; nt++)
                mx = fmaxf(mx, fmaxf(acc[mt][nt][2 * hi], acc[mt][nt][2 * hi + 1]));
            mx = fmaxf(mx, __shfl_xor_sync(~0u, mx, 1));
            mx = fmaxf(mx, __shfl_xor_sync(~0u, mx, 2));
            if (t == 0) pmax[(wm * 32 + mt * 16 + 8 * hi + g) * 2 + wn] = mx;
        }
    __syncthreads();

    #pragma unroll
    for (int mt = 0; mt < 2; mt++)
        #pragma unroll
        for (int hi = 0; hi < 2; hi++) {
            int row = wm * 32 + mt * 16 + 8 * hi + g;
            float tm = fmaxf(pmax[row * 2], pmax[row * 2 + 1]);
            float ls = 0.f;
            #pragma unroll
            for (int nt = 0; nt < 8; nt++)
                ls += __expf(acc[mt][nt][2 * hi] - tm) +
                      __expf(acc[mt][nt][2 * hi + 1] - tm);
            ls += __shfl_xor_sync(~0u, ls, 1);
            ls += __shfl_xor_sync(~0u, ls, 2);
            if (t == 0) psum[row * 2 + wn] = ls;
        }
    __syncthreads();

    if (tid < 128) {
        float m = fmaxf(pmax[tid * 2], pmax[tid * 2 + 1]);
        float ssum = psum[tid * 2] + psum[tid * 2 + 1];
        size_t idx = ((size_t)z * SS + q0 + tid) * KT + ktile;
        pm[idx] = m;
        ps[idx] = ssum;
    }
}

// ---------------------------------------------------------------------------
// Fused normalize + AV (round-8 proven, minus V cvts): K-tile 64, 2-stage
// cp.async, 2 CTAs/SM, inline stats combine. V pre-rounded tf32.
// ctx output written tf32-rounded (consumed only by outproj MMA).
// ---------------------------------------------------------------------------
#define PS_STR 68
#define VS_STR 72
#define AV_STG_F (128 * PS_STR + 64 * VS_STR)   // 13312 floats/stage
#define AV_SMEM_BYTES (2 * AV_STG_F * 4)        // 106496

__device__ __forceinline__ void av_load_tile(const float* __restrict__ attn,
                                             const float* __restrict__ V,
                                             int z, int b, int h, int q0, int k0,
                                             float* stage) {
    const int tid = threadIdx.x;
    unsigned sP = smem_u32(stage);
    unsigned sV = smem_u32(stage + 128 * PS_STR);
    #pragma unroll
    for (int i = tid; i < 2048; i += 256) {       // 128 x 64 floats
        int r = i >> 4, c4 = (i & 15) * 4;
        cpasync16(sP + (r * PS_STR + c4) * 4,
                  attn + ((size_t)z * SS + q0 + r) * SS + k0 + c4);
    }
    #pragma unroll
    for (int i = tid; i < 1024; i += 256) {       // 64 x 64 floats
        int r = i >> 4, c4 = (i & 15) * 4;
        cpasync16(sV + (r * VS_STR + c4) * 4,
                  V + (size_t)(b * SS + k0 + r) * DD + h * DP + c4);
    }
    asm volatile("cp.async.commit_group;");
}

__global__ void __launch_bounds__(256, 2)
attn_av_norm(float* __restrict__ attn,
             const float* __restrict__ V,
             const float* __restrict__ pm,
             const float* __restrict__ ps,
             float* __restrict__ C) {
    extern __shared__ float smf[];
    __shared__ float rs[128], ri[128];

    const int z = blockIdx.y;
    const int b = z >> 4;
    const int h = z & 15;
    const int q0 = blockIdx.x * 128;
    const int tid = threadIdx.x;
    const int warp = tid >> 5, lane = tid & 31;
    const int g = lane >> 2, t = lane & 3;
    const int wm = warp >> 1, wn = warp & 1;

    av_load_tile(attn, V, z, b, h, q0, 0, smf);

    // inline combine of per-tile stats (one thread per row)
    if (tid < 128) {
        size_t base = ((size_t)z * SS + q0 + tid) * KT;
        float M = -1e30f;
        #pragma unroll
        for (int j = 0; j < KT; j++) M = fmaxf(M, pm[base + j]);
        float S = 0.f;
        #pragma unroll
        for (int j = 0; j < KT; j++) S += ps[base + j] * __expf(pm[base + j] - M);
        rs[tid] = M;
        ri[tid] = 1.0f / S;
    }

    float acc[2][4][4] = {};
    int s = 0;
    for (int k0 = 0; k0 < SS; k0 += 64, s ^= 1) {
        if (k0 + 64 < SS) {
            av_load_tile(attn, V, z, b, h, q0, k0 + 64, smf + (s ^ 1) * AV_STG_F);
            asm volatile("cp.async.wait_group 1;");
        } else {
            asm volatile("cp.async.wait_group 0;");
        }
        __syncthreads();

        float* stage = smf + s * AV_STG_F;
        unsigned* stage_u = (unsigned*)stage;
        const unsigned* Vs = (const unsigned*)(stage + 128 * PS_STR);

        // exp + normalize: write global attn, overwrite smem with tf32 p
        #pragma unroll
        for (int i = tid; i < 2048; i += 256) {
            int r = i >> 4, c4 = (i & 15) * 4;
            float4 x = *(float4*)(stage + r * PS_STR + c4);
            float m = rs[r], inv = ri[r];
            x.x = __expf(x.x - m) * inv;
            x.y = __expf(x.y - m) * inv;
            x.z = __expf(x.z - m) * inv;
            x.w = __expf(x.w - m) * inv;
            *(float4*)(attn + ((size_t)z * SS + q0 + r) * SS + k0 + c4) = x;
            stage_u[r * PS_STR + c4 + 0] = f2tf(x.x);
            stage_u[r * PS_STR + c4 + 1] = f2tf(x.y);
            stage_u[r * PS_STR + c4 + 2] = f2tf(x.z);
            stage_u[r * PS_STR + c4 + 3] = f2tf(x.w);
        }
        __syncthreads();

        #pragma unroll
        for (int kk = 0; kk < 64; kk += 8) {
            unsigned a[2][4], bfr[4][2];
            #pragma unroll
            for (int mt = 0; mt < 2; mt++) {
                int m = wm * 32 + mt * 16;
                a[mt][0] = stage_u[(m + g) * PS_STR + kk + t];
                a[mt][1] = stage_u[(m + g + 8) * PS_STR + kk + t];
                a[mt][2] = stage_u[(m + g) * PS_STR + kk + t + 4];
                a[mt][3] = stage_u[(m + g + 8) * PS_STR + kk + t + 4];
            }
            #pragma unroll
            for (int nt = 0; nt < 4; nt++) {
                int n = wn * 32 + nt * 8 + g;
                bfr[nt][0] = Vs[(kk + t) * VS_STR + n];
                bfr[nt][1] = Vs[(kk + t + 4) * VS_STR + n];
            }
            #pragma unroll
            for (int mt = 0; mt < 2; mt++)
                #pragma unroll
                for (int nt = 0; nt < 4; nt++)
                    mma8(acc[mt][nt], a[mt], bfr[nt]);
        }
        __syncthreads();
    }

    #pragma unroll
    for (int mt = 0; mt < 2; mt++) {
        int qi = q0 + wm * 32 + mt * 16 + g;
        size_t base0 = (size_t)(b * SS + qi) * DD + h * DP;
        size_t base1 = base0 + (size_t)8 * DD;
        #pragma unroll
        for (int nt = 0; nt < 4; nt++) {
            int dj = wn * 32 + nt * 8 + 2 * t;
            C[base0 + dj]     = f2tff(acc[mt][nt][0]);
            C[base0 + dj + 1] = f2tff(acc[mt][nt][1]);
            C[base1 + dj]     = f2tff(acc[mt][nt][2]);
            C[base1 + dj + 1] = f2tff(acc[mt][nt][3]);
        }
    }
}

// ---------------------------------------------------------------------------
extern "C" void kernel_launch(void* const* d_in, const int* in_sizes, int n_in,
                              void* d_out, int out_size) {
    const float* q    = (const float*)d_in[0];
    const float* k    = (const float*)d_in[1];
    const float* v    = (const float*)d_in[2];
    const float* mask = (const float*)d_in[3];
    const float* Wq   = (const float*)d_in[4];
    const float* bq   = (const float*)d_in[5];
    const float* Wk   = (const float*)d_in[6];
    const float* bk   = (const float*)d_in[7];
    const float* Wv   = (const float*)d_in[8];
    const float* bv   = (const float*)d_in[9];
    const float* Wo   = (const float*)d_in[10];
    const float* bo   = (const float*)d_in[11];

    float* out  = (float*)d_out;
    float* attn = out + (size_t)MM * DD;   // output layout: (out, attn)

    float *pq, *pk, *pv, *pc, *piq, *pik, *piv, *pwt, *ppm, *pps;
    cudaGetSymbolAddress((void**)&pq, g_q);
    cudaGetSymbolAddress((void**)&pk, g_k);
    cudaGetSymbolAddress((void**)&pv, g_v);
    cudaGetSymbolAddress((void**)&pc, g_c);
    cudaGetSymbolAddress((void**)&piq, g_iq);
    cudaGetSymbolAddress((void**)&pik, g_ik);
    cudaGetSymbolAddress((void**)&piv, g_iv);
    cudaGetSymbolAddress((void**)&pwt, g_wt);
    cudaGetSymbolAddress((void**)&ppm, g_pm);
    cudaGetSymbolAddress((void**)&pps, g_ps);

    cudaFuncSetAttribute(qkv_gemm_tc, cudaFuncAttributeMaxDynamicSharedMemorySize,
                         GEMM_SMEM_BYTES);
    cudaFuncSetAttribute(sgemm_bias_tc, cudaFuncAttributeMaxDynamicSharedMemorySize,
                         GEMM_SMEM_BYTES);
    cudaFuncSetAttribute(attn_scores_tc, cudaFuncAttributeMaxDynamicSharedMemorySize,
                         SCORES_SMEM_BYTES);
    cudaFuncSetAttribute(attn_av_norm, cudaFuncAttributeMaxDynamicSharedMemorySize,
                         AV_SMEM_BYTES);

    // tf32 pre-rounding of all MMA inputs
    dim3 gCvt(MM * DD / (256 * 4), 7);              // (4096, 7)
    cvt_all<<<gCvt, 256>>>(q, k, v, Wq, Wk, Wv, Wo, piq, pik, piv, pwt);

    dim3 gQKV(DD / 128, MM / 128, 3);               // (8, 32, 3)
    qkv_gemm_tc<<<gQKV, 256, GEMM_SMEM_BYTES>>>(piq, pik, piv, pwt,
                                                bq, bk, bv, pq, pk, pv);

    dim3 gScores(SS / 128, SS / 128, NZ);           // (16, 16, 32)
    attn_scores_tc<<<gScores, 256, SCORES_SMEM_BYTES>>>(pq, pk, mask, attn, ppm, pps);

    dim3 gAV(SS / 128, NZ);                         // (16, 32)
    attn_av_norm<<<gAV, 256, AV_SMEM_BYTES>>>(attn, pv, ppm, pps, pc);

    dim3 gProj(DD / 128, MM / 128);                 // (8, 32)
    sgemm_bias_tc<<<gProj, 256, GEMM_SMEM_BYTES>>>(pc, pwt + (size_t)3 * DD * DD,
                                                   bo, out, DD, DD);
}